// round 2
// baseline (speedup 1.0000x reference)
#include <cuda_runtime.h>
#include <cuda_bf16.h>
#include <math.h>

// ---------------- problem constants ----------------
#define VOCAB    32000
#define DMODEL   256
#define DSTATE   64
#define DCONV    4
#define DINNER   1024
#define HEADDIM  64
#define NHEADS   16
#define CONVDIM  1152           // DINNER + 2*DSTATE
#define DPROJ    2192           // 2*DINNER + 2*DSTATE + NHEADS
#define BSZ      2
#define SEQ      512
#define NTOK     1024           // BSZ*SEQ
#define NLAYERS  2

// ---------------- scratch (no allocations allowed) ----------------
__device__ float g_h [NTOK * DMODEL];     // residual stream / layer io
__device__ float g_zx[NTOK * DPROJ];      // in_proj output
__device__ float g_xbc[NTOK * CONVDIM];   // conv+silu output
__device__ float g_dt[NTOK * NHEADS];
__device__ float g_dA[NTOK * NHEADS];
__device__ float g_ys[NTOK * DINNER];     // scan output (+ xh*D)
__device__ float g_y [NTOK * DINNER];     // gated + normed

// ---------------- kernels ----------------
__global__ void embed_kernel(const int* __restrict__ x, const float* __restrict__ emb) {
    int t = blockIdx.x;
    int d = threadIdx.x;
    g_h[t * DMODEL + d] = emb[x[t] * DMODEL + d];
}

// C[M,N] = A[M,K] * B[N,K]^T (+ bias[N]).  M multiple of 64, K multiple of 16.
#define BM 64
#define BN 64
#define BK 16
__global__ __launch_bounds__(256) void gemm_abt(
    const float* __restrict__ A, const float* __restrict__ B,
    const float* __restrict__ bias, float* __restrict__ C,
    int M, int N, int K)
{
    __shared__ float As[BK][BM + 1];
    __shared__ float Bs[BK][BN + 1];
    int tid = threadIdx.x;
    int bm = blockIdx.y * BM;
    int bn = blockIdx.x * BN;
    int tx = tid & 15, ty = tid >> 4;
    int tm = ty * 4, tn = tx * 4;
    float acc[4][4] = {};

    for (int k0 = 0; k0 < K; k0 += BK) {
        #pragma unroll
        for (int i = 0; i < 4; i++) {
            int lin = tid + i * 256;
            int m = lin >> 4, kk = lin & 15;
            As[kk][m] = A[(bm + m) * K + k0 + kk];
        }
        #pragma unroll
        for (int i = 0; i < 4; i++) {
            int lin = tid + i * 256;
            int n = lin >> 4, kk = lin & 15;
            int gn = bn + n;
            Bs[kk][n] = (gn < N) ? B[(size_t)gn * K + k0 + kk] : 0.f;
        }
        __syncthreads();
        #pragma unroll
        for (int kk = 0; kk < BK; kk++) {
            float a0 = As[kk][tm + 0], a1 = As[kk][tm + 1];
            float a2 = As[kk][tm + 2], a3 = As[kk][tm + 3];
            float b0 = Bs[kk][tn + 0], b1 = Bs[kk][tn + 1];
            float b2 = Bs[kk][tn + 2], b3 = Bs[kk][tn + 3];
            acc[0][0] += a0 * b0; acc[0][1] += a0 * b1; acc[0][2] += a0 * b2; acc[0][3] += a0 * b3;
            acc[1][0] += a1 * b0; acc[1][1] += a1 * b1; acc[1][2] += a1 * b2; acc[1][3] += a1 * b3;
            acc[2][0] += a2 * b0; acc[2][1] += a2 * b1; acc[2][2] += a2 * b2; acc[2][3] += a2 * b3;
            acc[3][0] += a3 * b0; acc[3][1] += a3 * b1; acc[3][2] += a3 * b2; acc[3][3] += a3 * b3;
        }
        __syncthreads();
    }
    #pragma unroll
    for (int i = 0; i < 4; i++) {
        int gm = bm + tm + i;
        #pragma unroll
        for (int j = 0; j < 4; j++) {
            int gn = bn + tn + j;
            if (gn < N) {
                float v = acc[i][j];
                if (bias) v += bias[gn];
                C[(size_t)gm * N + gn] = v;
            }
        }
    }
}

__device__ __forceinline__ float siluf(float x) {
    return x / (1.f + expf(-x));
}

// causal depthwise conv over xBC slice of g_zx, then silu -> g_xbc
__global__ void conv_silu_kernel(const float* __restrict__ convw,
                                 const float* __restrict__ convb)
{
    int idx = blockIdx.x * blockDim.x + threadIdx.x;
    if (idx >= NTOK * CONVDIM) return;
    int t = idx / CONVDIM;
    int c = idx - t * CONVDIM;
    int l = t & (SEQ - 1);
    float acc = convb[c];
    #pragma unroll
    for (int j = 0; j < DCONV; j++) {
        int li = l - (DCONV - 1) + j;
        if (li >= 0)
            acc += convw[c * DCONV + j] * g_zx[(t - (DCONV - 1) + j) * DPROJ + DINNER + c];
    }
    g_xbc[idx] = siluf(acc);
}

__global__ void dt_prep_kernel(const float* __restrict__ dt_bias,
                               const float* __restrict__ A_log)
{
    int idx = blockIdx.x * blockDim.x + threadIdx.x;
    if (idx >= NTOK * NHEADS) return;
    int t = idx >> 4;
    int h = idx & 15;
    float v = g_zx[t * DPROJ + (DINNER + CONVDIM) + h] + dt_bias[h];
    float dt = (v > 20.f) ? v : log1pf(expf(v));
    float A = -expf(A_log[h]);
    g_dt[idx] = dt;
    g_dA[idx] = expf(dt * A);
}

// sequential SSM scan: one block per (batch, head), 64 threads = HEADDIM rows
__global__ __launch_bounds__(64) void scan_kernel(const float* __restrict__ Dp)
{
    int bh = blockIdx.x;
    int b = bh >> 4;
    int h = bh & 15;
    int p = threadIdx.x;
    float hs[DSTATE];
    #pragma unroll
    for (int n = 0; n < DSTATE; n++) hs[n] = 0.f;
    __shared__ float Bs[DSTATE], Cs[DSTATE];
    float Dv = Dp[h];

    for (int l = 0; l < SEQ; l++) {
        int t = b * SEQ + l;
        float dA = g_dA[t * NHEADS + h];
        float dt = g_dt[t * NHEADS + h];
        float xh = g_xbc[t * CONVDIM + h * HEADDIM + p];
        Bs[p] = g_xbc[t * CONVDIM + DINNER + p];
        Cs[p] = g_xbc[t * CONVDIM + DINNER + DSTATE + p];
        __syncthreads();
        float dx = dt * xh;
        float y = 0.f;
        #pragma unroll
        for (int n = 0; n < DSTATE; n++) {
            hs[n] = hs[n] * dA + dx * Bs[n];
            y += hs[n] * Cs[n];
        }
        g_ys[t * DINNER + h * HEADDIM + p] = y + xh * Dv;
        __syncthreads();
    }
}

// y = ys * silu(z); RMSNorm over DINNER; * norm_w   (one block per token)
__global__ __launch_bounds__(256) void gate_norm_kernel(const float* __restrict__ norm_w)
{
    int t = blockIdx.x;
    int tid = threadIdx.x;
    float v[4];
    float ss = 0.f;
    #pragma unroll
    for (int i = 0; i < 4; i++) {
        int e = tid + i * 256;
        float z = g_zx[t * DPROJ + e];
        float vv = g_ys[t * DINNER + e] * siluf(z);
        v[i] = vv;
        ss += vv * vv;
    }
    __shared__ float red[256];
    red[tid] = ss;
    __syncthreads();
    for (int s = 128; s > 0; s >>= 1) {
        if (tid < s) red[tid] += red[tid + s];
        __syncthreads();
    }
    float scale = rsqrtf(red[0] / (float)DINNER + 1e-5f);
    #pragma unroll
    for (int i = 0; i < 4; i++) {
        int e = tid + i * 256;
        g_y[t * DINNER + e] = v[i] * scale * norm_w[e];
    }
}

// ---------------- host launch ----------------
extern "C" void kernel_launch(void* const* d_in, const int* in_sizes, int n_in,
                              void* d_out, int out_size)
{
    const int*   x       = (const int*)  d_in[0];
    const float* emb     = (const float*)d_in[1];
    const float* Win     = (const float*)d_in[2];   // (2, 2192, 256)
    const float* convw   = (const float*)d_in[3];   // (2, 1152, 4)
    const float* convb   = (const float*)d_in[4];   // (2, 1152)
    const float* dt_bias = (const float*)d_in[5];   // (2, 16)
    const float* A_log   = (const float*)d_in[6];   // (2, 16)
    const float* Dp      = (const float*)d_in[7];   // (2, 16)
    const float* norm_w  = (const float*)d_in[8];   // (2, 1024)
    const float* Wout    = (const float*)d_in[9];   // (2, 256, 1024)
    const float* Wlm     = (const float*)d_in[10];  // (32000, 256)
    const float* blm     = (const float*)d_in[11];  // (32000,)
    float* out = (float*)d_out;

    float* zx  = nullptr; cudaGetSymbolAddress((void**)&zx,  g_zx);
    float* hbuf= nullptr; cudaGetSymbolAddress((void**)&hbuf,g_h);
    float* ybuf= nullptr; cudaGetSymbolAddress((void**)&ybuf,g_y);

    embed_kernel<<<NTOK, DMODEL>>>(x, emb);

    for (int l = 0; l < NLAYERS; l++) {
        // in_proj: (1024 x 2192) = h (1024x256) * Win[l]^T
        gemm_abt<<<dim3((DPROJ + BN - 1) / BN, NTOK / BM), 256>>>(
            hbuf, Win + (size_t)l * DPROJ * DMODEL, nullptr, zx,
            NTOK, DPROJ, DMODEL);

        conv_silu_kernel<<<(NTOK * CONVDIM + 255) / 256, 256>>>(
            convw + (size_t)l * CONVDIM * DCONV, convb + (size_t)l * CONVDIM);

        dt_prep_kernel<<<(NTOK * NHEADS + 255) / 256, 256>>>(
            dt_bias + l * NHEADS, A_log + l * NHEADS);

        scan_kernel<<<BSZ * NHEADS, HEADDIM>>>(Dp + l * NHEADS);

        gate_norm_kernel<<<NTOK, 256>>>(norm_w + (size_t)l * DINNER);

        // out_proj: (1024 x 256) = y (1024x1024) * Wout[l]^T
        gemm_abt<<<dim3((DMODEL + BN - 1) / BN, NTOK / BM), 256>>>(
            ybuf, Wout + (size_t)l * DMODEL * DINNER, nullptr, hbuf,
            NTOK, DMODEL, DINNER);
    }

    // LM head: (1024 x 32000) = h (1024x256) * Wlm^T + blm
    gemm_abt<<<dim3(VOCAB / BN, NTOK / BM), 256>>>(
        hbuf, Wlm, blm, out, NTOK, VOCAB, DMODEL);
}

// round 3
// speedup vs baseline: 1.3321x; 1.3321x over previous
#include <cuda_runtime.h>
#include <cuda_bf16.h>
#include <math.h>

// ---------------- problem constants ----------------
#define VOCAB    32000
#define DMODEL   256
#define DSTATE   64
#define DCONV    4
#define DINNER   1024
#define HEADDIM  64
#define NHEADS   16
#define CONVDIM  1152           // DINNER + 2*DSTATE
#define DPROJ    2192           // 2*DINNER + 2*DSTATE + NHEADS
#define BSZ      2
#define SEQ      512
#define NTOK     1024           // BSZ*SEQ
#define NLAYERS  2

// ---------------- scratch (no allocations allowed) ----------------
__device__ float g_h [NTOK * DMODEL];     // residual stream / layer io
__device__ float g_zx[NTOK * DPROJ];      // in_proj output
__device__ float g_xbc[NTOK * CONVDIM];   // conv+silu output
__device__ float g_dt[NTOK * NHEADS];
__device__ float g_dA[NTOK * NHEADS];
__device__ float g_ys[NTOK * DINNER];     // scan output (+ xh*D)
__device__ float g_y [NTOK * DINNER];     // gated + normed

// ---------------- kernels ----------------
__global__ void embed_kernel(const int* __restrict__ x, const float* __restrict__ emb) {
    int t = blockIdx.x;
    int d = threadIdx.x;
    g_h[t * DMODEL + d] = emb[x[t] * DMODEL + d];
}

// ================= 128x128x8 SGEMM, C[M,N] = A[M,K]*B[N,K]^T (+bias) =======
// 256 threads, 8x8 micro-tile in split-half layout (4+4 at stride 64) so all
// compute-phase LDS.128 are bank-conflict-free. Global->reg prefetch.
#define TBM 128
#define TBN 128
#define TBK 8
__global__ __launch_bounds__(256) void gemm128(
    const float* __restrict__ A, const float* __restrict__ B,
    const float* __restrict__ bias, float* __restrict__ C,
    int M, int N, int K)
{
    __shared__ float As[TBK][TBM];
    __shared__ float Bs[TBK][TBN];
    int tid = threadIdx.x;
    int bm = blockIdx.y * TBM;
    int bn = blockIdx.x * TBN;

    int lr = tid >> 1;            // 0..127 row within tile
    int lk = (tid & 1) * 4;       // 0 or 4
    const float* Aptr = A + (size_t)(bm + lr) * K + lk;
    const float* Bptr = B + (size_t)(bn + lr) * K + lk;
    bool bvalid = (bn + lr) < N;

    int tx = tid & 15;            // -> n
    int ty = tid >> 4;            // -> m

    float acc[8][8];
    #pragma unroll
    for (int i = 0; i < 8; i++)
        #pragma unroll
        for (int j = 0; j < 8; j++) acc[i][j] = 0.f;

    float4 av = *(const float4*)(Aptr);
    float4 bv = bvalid ? *(const float4*)(Bptr) : make_float4(0.f,0.f,0.f,0.f);

    for (int k0 = 0; k0 < K; k0 += TBK) {
        As[lk+0][lr] = av.x; As[lk+1][lr] = av.y; As[lk+2][lr] = av.z; As[lk+3][lr] = av.w;
        Bs[lk+0][lr] = bv.x; Bs[lk+1][lr] = bv.y; Bs[lk+2][lr] = bv.z; Bs[lk+3][lr] = bv.w;
        __syncthreads();

        int kn = k0 + TBK;
        if (kn < K) {
            av = *(const float4*)(Aptr + kn);
            bv = bvalid ? *(const float4*)(Bptr + kn) : make_float4(0.f,0.f,0.f,0.f);
        }

        #pragma unroll
        for (int kk = 0; kk < TBK; kk++) {
            float4 a0 = *(const float4*)&As[kk][ty * 4];
            float4 a1 = *(const float4*)&As[kk][64 + ty * 4];
            float4 b0 = *(const float4*)&Bs[kk][tx * 4];
            float4 b1 = *(const float4*)&Bs[kk][64 + tx * 4];
            float ar[8] = {a0.x,a0.y,a0.z,a0.w,a1.x,a1.y,a1.z,a1.w};
            float br[8] = {b0.x,b0.y,b0.z,b0.w,b1.x,b1.y,b1.z,b1.w};
            #pragma unroll
            for (int i = 0; i < 8; i++)
                #pragma unroll
                for (int j = 0; j < 8; j++)
                    acc[i][j] += ar[i] * br[j];
        }
        __syncthreads();
    }

    bool fullN = (bn + TBN <= N);
    #pragma unroll
    for (int ih = 0; ih < 2; ih++) {
        #pragma unroll
        for (int i = 0; i < 4; i++) {
            int gm = bm + ih * 64 + ty * 4 + i;
            float* Crow = C + (size_t)gm * N;
            #pragma unroll
            for (int jh = 0; jh < 2; jh++) {
                int gn = bn + jh * 64 + tx * 4;
                float4 v;
                v.x = acc[ih*4+i][jh*4+0];
                v.y = acc[ih*4+i][jh*4+1];
                v.z = acc[ih*4+i][jh*4+2];
                v.w = acc[ih*4+i][jh*4+3];
                if (fullN) {
                    if (bias) {
                        v.x += bias[gn+0]; v.y += bias[gn+1];
                        v.z += bias[gn+2]; v.w += bias[gn+3];
                    }
                    *(float4*)(Crow + gn) = v;
                } else {
                    float vv[4] = {v.x, v.y, v.z, v.w};
                    #pragma unroll
                    for (int j = 0; j < 4; j++) {
                        if (gn + j < N) {
                            float o = vv[j];
                            if (bias) o += bias[gn + j];
                            Crow[gn + j] = o;
                        }
                    }
                }
            }
        }
    }
}

// ================= 64x64x16 SGEMM (kept for small-N out_proj) ==============
#define BM 64
#define BN 64
#define BK 16
__global__ __launch_bounds__(256) void gemm_abt(
    const float* __restrict__ A, const float* __restrict__ B,
    const float* __restrict__ bias, float* __restrict__ C,
    int M, int N, int K)
{
    __shared__ float As[BK][BM + 1];
    __shared__ float Bs[BK][BN + 1];
    int tid = threadIdx.x;
    int bm = blockIdx.y * BM;
    int bn = blockIdx.x * BN;
    int tx = tid & 15, ty = tid >> 4;
    int tm = ty * 4, tn = tx * 4;
    float acc[4][4] = {};

    for (int k0 = 0; k0 < K; k0 += BK) {
        #pragma unroll
        for (int i = 0; i < 4; i++) {
            int lin = tid + i * 256;
            int m = lin >> 4, kk = lin & 15;
            As[kk][m] = A[(bm + m) * K + k0 + kk];
        }
        #pragma unroll
        for (int i = 0; i < 4; i++) {
            int lin = tid + i * 256;
            int n = lin >> 4, kk = lin & 15;
            int gn = bn + n;
            Bs[kk][n] = (gn < N) ? B[(size_t)gn * K + k0 + kk] : 0.f;
        }
        __syncthreads();
        #pragma unroll
        for (int kk = 0; kk < BK; kk++) {
            float a0 = As[kk][tm + 0], a1 = As[kk][tm + 1];
            float a2 = As[kk][tm + 2], a3 = As[kk][tm + 3];
            float b0 = Bs[kk][tn + 0], b1 = Bs[kk][tn + 1];
            float b2 = Bs[kk][tn + 2], b3 = Bs[kk][tn + 3];
            acc[0][0] += a0 * b0; acc[0][1] += a0 * b1; acc[0][2] += a0 * b2; acc[0][3] += a0 * b3;
            acc[1][0] += a1 * b0; acc[1][1] += a1 * b1; acc[1][2] += a1 * b2; acc[1][3] += a1 * b3;
            acc[2][0] += a2 * b0; acc[2][1] += a2 * b1; acc[2][2] += a2 * b2; acc[2][3] += a2 * b3;
            acc[3][0] += a3 * b0; acc[3][1] += a3 * b1; acc[3][2] += a3 * b2; acc[3][3] += a3 * b3;
        }
        __syncthreads();
    }
    #pragma unroll
    for (int i = 0; i < 4; i++) {
        int gm = bm + tm + i;
        #pragma unroll
        for (int j = 0; j < 4; j++) {
            int gn = bn + tn + j;
            if (gn < N) {
                float v = acc[i][j];
                if (bias) v += bias[gn];
                C[(size_t)gm * N + gn] = v;
            }
        }
    }
}

__device__ __forceinline__ float siluf(float x) {
    return x / (1.f + expf(-x));
}

// causal depthwise conv over xBC slice of g_zx, then silu -> g_xbc
__global__ void conv_silu_kernel(const float* __restrict__ convw,
                                 const float* __restrict__ convb)
{
    int idx = blockIdx.x * blockDim.x + threadIdx.x;
    if (idx >= NTOK * CONVDIM) return;
    int t = idx / CONVDIM;
    int c = idx - t * CONVDIM;
    int l = t & (SEQ - 1);
    float acc = convb[c];
    #pragma unroll
    for (int j = 0; j < DCONV; j++) {
        int li = l - (DCONV - 1) + j;
        if (li >= 0)
            acc += convw[c * DCONV + j] * g_zx[(t - (DCONV - 1) + j) * DPROJ + DINNER + c];
    }
    g_xbc[idx] = siluf(acc);
}

__global__ void dt_prep_kernel(const float* __restrict__ dt_bias,
                               const float* __restrict__ A_log)
{
    int idx = blockIdx.x * blockDim.x + threadIdx.x;
    if (idx >= NTOK * NHEADS) return;
    int t = idx >> 4;
    int h = idx & 15;
    float v = g_zx[t * DPROJ + (DINNER + CONVDIM) + h] + dt_bias[h];
    float dt = (v > 20.f) ? v : log1pf(expf(v));
    float A = -expf(A_log[h]);
    g_dt[idx] = dt;
    g_dA[idx] = expf(dt * A);
}

// sequential SSM scan: one block per (batch, head).
// 128 threads: p = tid&63 (headdim row), half = tid>>6 selects 32 of the 64
// states. Per step each thread does 32 fused update+readout FMA pairs against
// float4 B/C from shared; halves combine through shared memory.
__global__ __launch_bounds__(128) void scan_kernel(const float* __restrict__ Dp)
{
    int bh = blockIdx.x;
    int b = bh >> 4;
    int h = bh & 15;
    int tid = threadIdx.x;
    int p = tid & 63;
    int half = tid >> 6;

    float hs[32];
    #pragma unroll
    for (int n = 0; n < 32; n++) hs[n] = 0.f;

    __shared__ float Bs[DSTATE], Cs[DSTATE], ysh[128];
    float Dv = Dp[h];

    for (int l = 0; l < SEQ; l++) {
        int t = b * SEQ + l;
        float dA = g_dA[t * NHEADS + h];
        float dt = g_dt[t * NHEADS + h];
        float xh = g_xbc[t * CONVDIM + h * HEADDIM + p];
        if (half == 0) Bs[p] = g_xbc[t * CONVDIM + DINNER + p];
        else           Cs[p] = g_xbc[t * CONVDIM + DINNER + DSTATE + p];
        __syncthreads();

        float dx = dt * xh;
        float y0 = 0.f, y1 = 0.f, y2 = 0.f, y3 = 0.f;
        const float4* B4 = (const float4*)(Bs + half * 32);
        const float4* C4 = (const float4*)(Cs + half * 32);
        #pragma unroll
        for (int n4 = 0; n4 < 8; n4++) {
            float4 bb = B4[n4];
            float4 cc = C4[n4];
            hs[n4*4+0] = hs[n4*4+0] * dA + dx * bb.x;  y0 += hs[n4*4+0] * cc.x;
            hs[n4*4+1] = hs[n4*4+1] * dA + dx * bb.y;  y1 += hs[n4*4+1] * cc.y;
            hs[n4*4+2] = hs[n4*4+2] * dA + dx * bb.z;  y2 += hs[n4*4+2] * cc.z;
            hs[n4*4+3] = hs[n4*4+3] * dA + dx * bb.w;  y3 += hs[n4*4+3] * cc.w;
        }
        ysh[tid] = (y0 + y1) + (y2 + y3);
        __syncthreads();

        if (half == 0)
            g_ys[t * DINNER + h * HEADDIM + p] = ysh[p] + ysh[p + 64] + xh * Dv;
    }
}

// y = ys * silu(z); RMSNorm over DINNER; * norm_w   (one block per token)
__global__ __launch_bounds__(256) void gate_norm_kernel(const float* __restrict__ norm_w)
{
    int t = blockIdx.x;
    int tid = threadIdx.x;
    float v[4];
    float ss = 0.f;
    #pragma unroll
    for (int i = 0; i < 4; i++) {
        int e = tid + i * 256;
        float z = g_zx[t * DPROJ + e];
        float vv = g_ys[t * DINNER + e] * siluf(z);
        v[i] = vv;
        ss += vv * vv;
    }
    __shared__ float red[256];
    red[tid] = ss;
    __syncthreads();
    for (int s = 128; s > 0; s >>= 1) {
        if (tid < s) red[tid] += red[tid + s];
        __syncthreads();
    }
    float scale = rsqrtf(red[0] / (float)DINNER + 1e-5f);
    #pragma unroll
    for (int i = 0; i < 4; i++) {
        int e = tid + i * 256;
        g_y[t * DINNER + e] = v[i] * scale * norm_w[e];
    }
}

// ---------------- host launch ----------------
extern "C" void kernel_launch(void* const* d_in, const int* in_sizes, int n_in,
                              void* d_out, int out_size)
{
    const int*   x       = (const int*)  d_in[0];
    const float* emb     = (const float*)d_in[1];
    const float* Win     = (const float*)d_in[2];   // (2, 2192, 256)
    const float* convw   = (const float*)d_in[3];   // (2, 1152, 4)
    const float* convb   = (const float*)d_in[4];   // (2, 1152)
    const float* dt_bias = (const float*)d_in[5];   // (2, 16)
    const float* A_log   = (const float*)d_in[6];   // (2, 16)
    const float* Dp      = (const float*)d_in[7];   // (2, 16)
    const float* norm_w  = (const float*)d_in[8];   // (2, 1024)
    const float* Wout    = (const float*)d_in[9];   // (2, 256, 1024)
    const float* Wlm     = (const float*)d_in[10];  // (32000, 256)
    const float* blm     = (const float*)d_in[11];  // (32000,)
    float* out = (float*)d_out;

    float* zx  = nullptr; cudaGetSymbolAddress((void**)&zx,  g_zx);
    float* hbuf= nullptr; cudaGetSymbolAddress((void**)&hbuf,g_h);
    float* ybuf= nullptr; cudaGetSymbolAddress((void**)&ybuf,g_y);

    embed_kernel<<<NTOK, DMODEL>>>(x, emb);

    for (int l = 0; l < NLAYERS; l++) {
        // in_proj: (1024 x 2192) = h (1024x256) * Win[l]^T
        gemm128<<<dim3((DPROJ + TBN - 1) / TBN, NTOK / TBM), 256>>>(
            hbuf, Win + (size_t)l * DPROJ * DMODEL, nullptr, zx,
            NTOK, DPROJ, DMODEL);

        conv_silu_kernel<<<(NTOK * CONVDIM + 255) / 256, 256>>>(
            convw + (size_t)l * CONVDIM * DCONV, convb + (size_t)l * CONVDIM);

        dt_prep_kernel<<<(NTOK * NHEADS + 255) / 256, 256>>>(
            dt_bias + l * NHEADS, A_log + l * NHEADS);

        scan_kernel<<<BSZ * NHEADS, 128>>>(Dp + l * NHEADS);

        gate_norm_kernel<<<NTOK, 256>>>(norm_w + (size_t)l * DINNER);

        // out_proj: (1024 x 256) = y (1024x1024) * Wout[l]^T  (small N -> 64x64 tiles)
        gemm_abt<<<dim3((DMODEL + BN - 1) / BN, NTOK / BM), 256>>>(
            ybuf, Wout + (size_t)l * DMODEL * DINNER, nullptr, hbuf,
            NTOK, DMODEL, DINNER);
    }

    // LM head: (1024 x 32000) = h (1024x256) * Wlm^T + blm
    gemm128<<<dim3(VOCAB / TBN, NTOK / TBM), 256>>>(
        hbuf, Wlm, blm, out, NTOK, VOCAB, DMODEL);
}

// round 4
// speedup vs baseline: 1.7542x; 1.3168x over previous
#include <cuda_runtime.h>
#include <cuda_bf16.h>
#include <math.h>
#include <stdint.h>

// ---------------- problem constants ----------------
#define VOCAB    32000
#define DMODEL   256
#define DSTATE   64
#define DCONV    4
#define DINNER   1024
#define HEADDIM  64
#define NHEADS   16
#define CONVDIM  1152           // DINNER + 2*DSTATE
#define DPROJ    2192           // 2*DINNER + 2*DSTATE + NHEADS
#define BSZ      2
#define SEQ      512
#define NTOK     1024           // BSZ*SEQ
#define NLAYERS  2

// ---------------- scratch (no allocations allowed) ----------------
__device__ float g_h [NTOK * DMODEL];     // residual stream / layer io
__device__ float g_zx[NTOK * DPROJ];      // in_proj output
__device__ float g_xbc[NTOK * CONVDIM];   // conv+silu output
__device__ float g_dt[NTOK * NHEADS];
__device__ float g_dA[NTOK * NHEADS];
__device__ float g_ys[NTOK * DINNER];     // scan output (+ xh*D)
__device__ float g_y [NTOK * DINNER];     // gated + normed

// split-bf16 staging (hi + lo so that hi+lo ~ fp32 value)
__device__ __nv_bfloat16 g_Ahi[NTOK * DINNER];
__device__ __nv_bfloat16 g_Alo[NTOK * DINNER];
__device__ __nv_bfloat16 g_Bhi[VOCAB * DMODEL];
__device__ __nv_bfloat16 g_Blo[VOCAB * DMODEL];

// ---------------- helpers ----------------
__device__ __forceinline__ uint32_t smem_u32(const void* p) {
    uint32_t a;
    asm("{ .reg .u64 t; cvta.to.shared.u64 t, %1; cvt.u32.u64 %0, t; }" : "=r"(a) : "l"(p));
    return a;
}
__device__ __forceinline__ void ldsm4(uint32_t a, uint32_t& r0, uint32_t& r1,
                                      uint32_t& r2, uint32_t& r3) {
    asm volatile("ldmatrix.sync.aligned.m8n8.x4.shared.b16 {%0,%1,%2,%3}, [%4];"
                 : "=r"(r0), "=r"(r1), "=r"(r2), "=r"(r3) : "r"(a));
}
__device__ __forceinline__ void mma_bf16(float* c, const uint32_t* a,
                                         uint32_t b0, uint32_t b1) {
    asm volatile("mma.sync.aligned.m16n8k16.row.col.f32.bf16.bf16.f32 "
                 "{%0,%1,%2,%3}, {%4,%5,%6,%7}, {%8,%9}, {%0,%1,%2,%3};"
                 : "+f"(c[0]), "+f"(c[1]), "+f"(c[2]), "+f"(c[3])
                 : "r"(a[0]), "r"(a[1]), "r"(a[2]), "r"(a[3]), "r"(b0), "r"(b1));
}
__device__ __forceinline__ void cp16(uint32_t dst, const void* src, int sz) {
    asm volatile("cp.async.cg.shared.global [%0], [%1], 16, %2;"
                 :: "r"(dst), "l"(src), "r"(sz));
}
__device__ __forceinline__ float siluf(float x) {
    return x / (1.f + expf(-x));
}

// ---------------- kernels ----------------
__global__ void embed_kernel(const int* __restrict__ x, const float* __restrict__ emb) {
    int t = blockIdx.x;
    int d = threadIdx.x;
    g_h[t * DMODEL + d] = emb[x[t] * DMODEL + d];
}

// fp32 -> (hi, lo) bf16 split, 4 elems per thread
__global__ void cvt_split_kernel(const float4* __restrict__ src,
                                 __nv_bfloat16* __restrict__ hi,
                                 __nv_bfloat16* __restrict__ lo, int n4) {
    int i = blockIdx.x * blockDim.x + threadIdx.x;
    if (i >= n4) return;
    float4 v = src[i];
    __nv_bfloat16 h0 = __float2bfloat16(v.x);
    __nv_bfloat16 h1 = __float2bfloat16(v.y);
    __nv_bfloat16 h2 = __float2bfloat16(v.z);
    __nv_bfloat16 h3 = __float2bfloat16(v.w);
    __nv_bfloat16 l0 = __float2bfloat16(v.x - __bfloat162float(h0));
    __nv_bfloat16 l1 = __float2bfloat16(v.y - __bfloat162float(h1));
    __nv_bfloat16 l2 = __float2bfloat16(v.z - __bfloat162float(h2));
    __nv_bfloat16 l3 = __float2bfloat16(v.w - __bfloat162float(h3));
    __nv_bfloat162* hp = (__nv_bfloat162*)hi;
    __nv_bfloat162* lp = (__nv_bfloat162*)lo;
    hp[2*i+0] = __nv_bfloat162(h0, h1);
    hp[2*i+1] = __nv_bfloat162(h2, h3);
    lp[2*i+0] = __nv_bfloat162(l0, l1);
    lp[2*i+1] = __nv_bfloat162(l2, l3);
}

// ======= split-bf16 tensor-core GEMM: C[M,N] = A[M,K]*B[N,K]^T (+bias) =======
// A,B given as hi/lo bf16 pairs; result = hi*hi + hi*lo + lo*hi in fp32 acc.
// Block tile BMt x BMt, k-chunk 16, double-buffered cp.async.
// SMEM rows padded to 24 bf16 (48B stride): ldmatrix conflict-free.
#define RS 24
template<int BMt, int WMW, int WNW>
__global__ void __launch_bounds__(2 * BMt) gemm_mma(
    const __nv_bfloat16* __restrict__ Ahi, const __nv_bfloat16* __restrict__ Alo,
    const __nv_bfloat16* __restrict__ Bhi, const __nv_bfloat16* __restrict__ Blo,
    const float* __restrict__ bias, float* __restrict__ C,
    int M, int N, int K)
{
    constexpr int BNt = BMt;
    constexpr int WTM = BMt / WMW;        // warp tile m
    constexpr int WTN = BNt / WNW;        // warp tile n
    constexpr int MT = WTM / 16;
    constexpr int NT = WTN / 8;
    constexpr int TILEB = BMt * RS * 2;   // bytes per (hi/lo A/B) tile
    constexpr int BUFB = 4 * TILEB;

    __shared__ __nv_bfloat16 sm[2 * 4 * BMt * RS];
    uint32_t smb = smem_u32(sm);

    int tid = threadIdx.x;
    int bm = blockIdx.y * BMt;
    int bn = blockIdx.x * BNt;

    // ---- cp.async plumbing: thread -> (row, 16B-half) of each of 4 tiles
    int row = tid >> 1, half = tid & 1;
    const __nv_bfloat16* s0 = Ahi + (size_t)(bm + row) * K + half * 8;
    const __nv_bfloat16* s1 = Alo + (size_t)(bm + row) * K + half * 8;
    int brow = bn + row;
    bool bval = brow < N;
    int bro = bval ? brow : 0;
    const __nv_bfloat16* s2 = Bhi + (size_t)bro * K + half * 8;
    const __nv_bfloat16* s3 = Blo + (size_t)bro * K + half * 8;
    int bsz = bval ? 16 : 0;
    uint32_t d0 = smb + (uint32_t)((row * RS + half * 8) * 2);

    int nk = K / 16;

    auto issue = [&](int ks, int buf) {
        int k0 = ks * 16;
        uint32_t bo = d0 + buf * BUFB;
        cp16(bo,             s0 + k0, 16);
        cp16(bo + TILEB,     s1 + k0, 16);
        cp16(bo + 2 * TILEB, s2 + k0, bsz);
        cp16(bo + 3 * TILEB, s3 + k0, bsz);
        asm volatile("cp.async.commit_group;");
    };

    // ---- ldmatrix addresses (buf 0)
    int lane = tid & 31, warp = tid >> 5;
    int wm = warp / WNW, wn = warp % WNW;
    uint32_t acol = (uint32_t)((lane >> 4) * 8);
    uint32_t a_addr[MT], b_addr[NT / 2];
    #pragma unroll
    for (int mt = 0; mt < MT; mt++) {
        int r = wm * WTM + mt * 16 + (lane & 15);
        a_addr[mt] = smb + (uint32_t)((r * RS) * 2) + acol * 2;
    }
    #pragma unroll
    for (int np = 0; np < NT / 2; np++) {
        int r = wn * WTN + np * 16 + (lane & 15);
        b_addr[np] = smb + 2 * TILEB + (uint32_t)((r * RS) * 2) + acol * 2;
    }

    float acc[MT][NT][4];
    #pragma unroll
    for (int i = 0; i < MT; i++)
        #pragma unroll
        for (int j = 0; j < NT; j++)
            #pragma unroll
            for (int q = 0; q < 4; q++) acc[i][j][q] = 0.f;

    issue(0, 0);
    for (int ks = 0; ks < nk; ks++) {
        int buf = ks & 1;
        if (ks + 1 < nk) {
            issue(ks + 1, buf ^ 1);
            asm volatile("cp.async.wait_group 1;");
        } else {
            asm volatile("cp.async.wait_group 0;");
        }
        __syncthreads();

        uint32_t bo = (uint32_t)(buf * BUFB);
        uint32_t ah[MT][4], al[MT][4], bh[NT][2], bl[NT][2];
        #pragma unroll
        for (int mt = 0; mt < MT; mt++) {
            ldsm4(a_addr[mt] + bo,         ah[mt][0], ah[mt][1], ah[mt][2], ah[mt][3]);
            ldsm4(a_addr[mt] + bo + TILEB, al[mt][0], al[mt][1], al[mt][2], al[mt][3]);
        }
        #pragma unroll
        for (int np = 0; np < NT / 2; np++) {
            uint32_t r0, r1, r2, r3;
            ldsm4(b_addr[np] + bo, r0, r1, r2, r3);
            bh[2*np][0] = r0; bh[2*np][1] = r2;
            bh[2*np+1][0] = r1; bh[2*np+1][1] = r3;
            ldsm4(b_addr[np] + bo + TILEB, r0, r1, r2, r3);
            bl[2*np][0] = r0; bl[2*np][1] = r2;
            bl[2*np+1][0] = r1; bl[2*np+1][1] = r3;
        }
        #pragma unroll
        for (int mt = 0; mt < MT; mt++)
            #pragma unroll
            for (int nt = 0; nt < NT; nt++) {
                mma_bf16(acc[mt][nt], ah[mt], bh[nt][0], bh[nt][1]);
                mma_bf16(acc[mt][nt], ah[mt], bl[nt][0], bl[nt][1]);
                mma_bf16(acc[mt][nt], al[mt], bh[nt][0], bh[nt][1]);
            }
        __syncthreads();
    }

    // ---- epilogue
    #pragma unroll
    for (int mt = 0; mt < MT; mt++) {
        int r0 = bm + wm * WTM + mt * 16 + (lane >> 2);
        #pragma unroll
        for (int nt = 0; nt < NT; nt++) {
            int cn = bn + wn * WTN + nt * 8 + 2 * (lane & 3);
            if (cn < N) {
                float bx = bias ? bias[cn]     : 0.f;
                float by = bias ? bias[cn + 1] : 0.f;
                float2 v0 = make_float2(acc[mt][nt][0] + bx, acc[mt][nt][1] + by);
                float2 v1 = make_float2(acc[mt][nt][2] + bx, acc[mt][nt][3] + by);
                *(float2*)&C[(size_t)r0 * N + cn]       = v0;
                *(float2*)&C[(size_t)(r0 + 8) * N + cn] = v1;
            }
        }
    }
}

// causal depthwise conv over xBC slice of g_zx, then silu -> g_xbc
__global__ void conv_silu_kernel(const float* __restrict__ convw,
                                 const float* __restrict__ convb)
{
    int idx = blockIdx.x * blockDim.x + threadIdx.x;
    if (idx >= NTOK * CONVDIM) return;
    int t = idx / CONVDIM;
    int c = idx - t * CONVDIM;
    int l = t & (SEQ - 1);
    float acc = convb[c];
    #pragma unroll
    for (int j = 0; j < DCONV; j++) {
        int li = l - (DCONV - 1) + j;
        if (li >= 0)
            acc += convw[c * DCONV + j] * g_zx[(t - (DCONV - 1) + j) * DPROJ + DINNER + c];
    }
    g_xbc[idx] = siluf(acc);
}

__global__ void dt_prep_kernel(const float* __restrict__ dt_bias,
                               const float* __restrict__ A_log)
{
    int idx = blockIdx.x * blockDim.x + threadIdx.x;
    if (idx >= NTOK * NHEADS) return;
    int t = idx >> 4;
    int h = idx & 15;
    float v = g_zx[t * DPROJ + (DINNER + CONVDIM) + h] + dt_bias[h];
    float dt = (v > 20.f) ? v : log1pf(expf(v));
    float A = -expf(A_log[h]);
    g_dt[idx] = dt;
    g_dA[idx] = expf(dt * A);
}

// sequential SSM scan: one block per (batch, head), 128 threads (2 state-halves)
__global__ void __launch_bounds__(128) scan_kernel(const float* __restrict__ Dp)
{
    int bh = blockIdx.x;
    int b = bh >> 4;
    int h = bh & 15;
    int tid = threadIdx.x;
    int p = tid & 63;
    int half = tid >> 6;

    float hs[32];
    #pragma unroll
    for (int n = 0; n < 32; n++) hs[n] = 0.f;

    __shared__ float Bs[DSTATE], Cs[DSTATE], ysh[128];
    float Dv = Dp[h];

    for (int l = 0; l < SEQ; l++) {
        int t = b * SEQ + l;
        float dA = g_dA[t * NHEADS + h];
        float dt = g_dt[t * NHEADS + h];
        float xh = g_xbc[t * CONVDIM + h * HEADDIM + p];
        if (half == 0) Bs[p] = g_xbc[t * CONVDIM + DINNER + p];
        else           Cs[p] = g_xbc[t * CONVDIM + DINNER + DSTATE + p];
        __syncthreads();

        float dx = dt * xh;
        float y0 = 0.f, y1 = 0.f, y2 = 0.f, y3 = 0.f;
        const float4* B4 = (const float4*)(Bs + half * 32);
        const float4* C4 = (const float4*)(Cs + half * 32);
        #pragma unroll
        for (int n4 = 0; n4 < 8; n4++) {
            float4 bb = B4[n4];
            float4 cc = C4[n4];
            hs[n4*4+0] = hs[n4*4+0] * dA + dx * bb.x;  y0 += hs[n4*4+0] * cc.x;
            hs[n4*4+1] = hs[n4*4+1] * dA + dx * bb.y;  y1 += hs[n4*4+1] * cc.y;
            hs[n4*4+2] = hs[n4*4+2] * dA + dx * bb.z;  y2 += hs[n4*4+2] * cc.z;
            hs[n4*4+3] = hs[n4*4+3] * dA + dx * bb.w;  y3 += hs[n4*4+3] * cc.w;
        }
        ysh[tid] = (y0 + y1) + (y2 + y3);
        __syncthreads();

        if (half == 0)
            g_ys[t * DINNER + h * HEADDIM + p] = ysh[p] + ysh[p + 64] + xh * Dv;
    }
}

// y = ys * silu(z); RMSNorm over DINNER; * norm_w   (one block per token)
__global__ void __launch_bounds__(256) gate_norm_kernel(const float* __restrict__ norm_w)
{
    int t = blockIdx.x;
    int tid = threadIdx.x;
    float v[4];
    float ss = 0.f;
    #pragma unroll
    for (int i = 0; i < 4; i++) {
        int e = tid + i * 256;
        float z = g_zx[t * DPROJ + e];
        float vv = g_ys[t * DINNER + e] * siluf(z);
        v[i] = vv;
        ss += vv * vv;
    }
    __shared__ float red[256];
    red[tid] = ss;
    __syncthreads();
    for (int s = 128; s > 0; s >>= 1) {
        if (tid < s) red[tid] += red[tid + s];
        __syncthreads();
    }
    float scale = rsqrtf(red[0] / (float)DINNER + 1e-5f);
    #pragma unroll
    for (int i = 0; i < 4; i++) {
        int e = tid + i * 256;
        g_y[t * DINNER + e] = v[i] * scale * norm_w[e];
    }
}

// ---------------- host launch ----------------
static inline void cvt_split(const float* src, __nv_bfloat16* hi, __nv_bfloat16* lo, int n) {
    int n4 = n / 4;
    cvt_split_kernel<<<(n4 + 255) / 256, 256>>>((const float4*)src, hi, lo, n4);
}

extern "C" void kernel_launch(void* const* d_in, const int* in_sizes, int n_in,
                              void* d_out, int out_size)
{
    const int*   x       = (const int*)  d_in[0];
    const float* emb     = (const float*)d_in[1];
    const float* Win     = (const float*)d_in[2];   // (2, 2192, 256)
    const float* convw   = (const float*)d_in[3];   // (2, 1152, 4)
    const float* convb   = (const float*)d_in[4];   // (2, 1152)
    const float* dt_bias = (const float*)d_in[5];   // (2, 16)
    const float* A_log   = (const float*)d_in[6];   // (2, 16)
    const float* Dp      = (const float*)d_in[7];   // (2, 16)
    const float* norm_w  = (const float*)d_in[8];   // (2, 1024)
    const float* Wout    = (const float*)d_in[9];   // (2, 256, 1024)
    const float* Wlm     = (const float*)d_in[10];  // (32000, 256)
    const float* blm     = (const float*)d_in[11];  // (32000,)
    float* out = (float*)d_out;

    float* zx  = nullptr; cudaGetSymbolAddress((void**)&zx,  g_zx);
    float* hbuf= nullptr; cudaGetSymbolAddress((void**)&hbuf,g_h);
    float* ybuf= nullptr; cudaGetSymbolAddress((void**)&ybuf,g_y);
    __nv_bfloat16 *ahi=nullptr, *alo=nullptr, *bhi=nullptr, *blo=nullptr;
    cudaGetSymbolAddress((void**)&ahi, g_Ahi);
    cudaGetSymbolAddress((void**)&alo, g_Alo);
    cudaGetSymbolAddress((void**)&bhi, g_Bhi);
    cudaGetSymbolAddress((void**)&blo, g_Blo);

    embed_kernel<<<NTOK, DMODEL>>>(x, emb);

    for (int l = 0; l < NLAYERS; l++) {
        // in_proj: (1024 x 2192) = h (1024x256) * Win[l]^T
        cvt_split(hbuf, ahi, alo, NTOK * DMODEL);
        cvt_split(Win + (size_t)l * DPROJ * DMODEL, bhi, blo, DPROJ * DMODEL);
        gemm_mma<128, 2, 4><<<dim3((DPROJ + 127) / 128, NTOK / 128), 256>>>(
            ahi, alo, bhi, blo, nullptr, zx, NTOK, DPROJ, DMODEL);

        conv_silu_kernel<<<(NTOK * CONVDIM + 255) / 256, 256>>>(
            convw + (size_t)l * CONVDIM * DCONV, convb + (size_t)l * CONVDIM);

        dt_prep_kernel<<<(NTOK * NHEADS + 255) / 256, 256>>>(
            dt_bias + l * NHEADS, A_log + l * NHEADS);

        scan_kernel<<<BSZ * NHEADS, 128>>>(Dp + l * NHEADS);

        gate_norm_kernel<<<NTOK, 256>>>(norm_w + (size_t)l * DINNER);

        // out_proj: (1024 x 256) = y (1024x1024) * Wout[l]^T
        cvt_split(ybuf, ahi, alo, NTOK * DINNER);
        cvt_split(Wout + (size_t)l * DMODEL * DINNER, bhi, blo, DMODEL * DINNER);
        gemm_mma<64, 2, 2><<<dim3(DMODEL / 64, NTOK / 64), 128>>>(
            ahi, alo, bhi, blo, nullptr, hbuf, NTOK, DMODEL, DINNER);
    }

    // LM head: (1024 x 32000) = h (1024x256) * Wlm^T + blm
    cvt_split(hbuf, ahi, alo, NTOK * DMODEL);
    cvt_split(Wlm, bhi, blo, VOCAB * DMODEL);
    gemm_mma<128, 2, 4><<<dim3(VOCAB / 128, NTOK / 128), 256>>>(
        ahi, alo, bhi, blo, blm, out, NTOK, VOCAB, DMODEL);
}